// round 4
// baseline (speedup 1.0000x reference)
#include <cuda_runtime.h>
#include <math.h>

#define D_ 96
#define H_ 192
#define W_ 192
#define B_ 2
#define VOL (D_*H_*W_)            // 3538944
#define RAD 12
#define KLEN 25
#define SLAB 16
#define NSLAB (D_/SLAB)           // 6
#define NPART ( (W_/32) * H_ )    // 1152 partials per batch (blurD grid x*y)

// ---- static scratch (device globals: the sanctioned no-alloc workaround) ----
__device__ float d_mag[B_*VOL];
__device__ float d_g  [B_*VOL];
__device__ float d_gauss[KLEN];
__device__ float d_pnum[B_*NPART];
__device__ float d_pden[B_*NPART];

// ---------------------------------------------------------------------------
// Gaussian kernel taps (MONAI gaussian_1d, approx='erf', sigma=3, tail=12)
__global__ void init_gauss_kernel() {
    int t = threadIdx.x;
    if (t < KLEN) {
        float x = (float)(t - RAD);
        const float c = 0.70710678f / 3.0f;
        float k = 0.5f * (erff(c * (x + 0.5f)) - erff(c * (x - 0.5f)));
        d_gauss[t] = fmaxf(k, 0.0f);
    }
}

// ---------------------------------------------------------------------------
// Fused: S = rint(o0)+rint(o1); Sobel (xv,xh in HW plane; xd over D,H); mag.
// Rolling 3-plane shared tiles, zero padding outside the volume.
__global__ __launch_bounds__(256) void sobel_mag_kernel(const float* __restrict__ outs) {
    __shared__ float sh[3][10][34];
    const int tx = threadIdx.x, ty = threadIdx.y;
    const int tid = ty * 32 + tx;
    const int w0 = blockIdx.x * 32, h0 = blockIdx.y * 8;
    const int bz = blockIdx.z;
    const int b = bz / NSLAB;
    const int d0 = (bz % NSLAB) * SLAB;
    const float* o0 = outs + (size_t)(b * 2 + 0) * VOL;
    const float* o1 = outs + (size_t)(b * 2 + 1) * VOL;

    auto loadPlane = [&](int d, int slot) {
        for (int i = tid; i < 340; i += 256) {
            int lh = i / 34, lw = i - lh * 34;
            int gh = h0 + lh - 1, gw = w0 + lw - 1;
            float s = 0.0f;
            if ((unsigned)d < (unsigned)D_ && (unsigned)gh < (unsigned)H_ &&
                (unsigned)gw < (unsigned)W_) {
                int idx = (d * H_ + gh) * W_ + gw;
                s = rintf(__ldg(o0 + idx)) + rintf(__ldg(o1 + idx));
            }
            sh[slot][lh][lw] = s;
        }
    };

    // plane p lives in slot (p+1) mod 3 (negative-safe since d0>=0)
    loadPlane(d0 - 1, d0 % 3);
    loadPlane(d0,     (d0 + 1) % 3);

    const int lh = ty + 1, lw = tx + 1;
    for (int d = d0; d < d0 + SLAB; d++) {
        loadPlane(d + 1, (d + 2) % 3);
        __syncthreads();
        const float (*P)[34] = sh[d % 3];        // d-1
        const float (*C)[34] = sh[(d + 1) % 3];  // d
        const float (*N)[34] = sh[(d + 2) % 3];  // d+1
        float c_mm = C[lh-1][lw-1], c_m0 = C[lh-1][lw], c_mp = C[lh-1][lw+1];
        float c_0m = C[lh  ][lw-1],                     c_0p = C[lh  ][lw+1];
        float c_pm = C[lh+1][lw-1], c_p0 = C[lh+1][lw], c_pp = C[lh+1][lw+1];
        float xv = (c_pm + 2.0f*c_p0 + c_pp) - (c_mm + 2.0f*c_m0 + c_mp);
        float xh = (c_mp + 2.0f*c_0p + c_pp) - (c_mm + 2.0f*c_0m + c_pm);
        float xd = (P[lh+1][lw] - P[lh-1][lw]) + 2.0f*(c_p0 - c_m0)
                 + (N[lh+1][lw] - N[lh-1][lw]);
        float mag = sqrtf(xv*xv + xh*xh + xd*xd + 1e-6f);
        d_mag[(size_t)b*VOL + ((size_t)d*H_ + (h0+ty))*W_ + (w0+tx)] = mag;
        __syncthreads();
    }
}

// ---------------------------------------------------------------------------
// Fused Gsum + blur along W.  One block per (h,d,b) row. Writes d_g.
__global__ __launch_bounds__(W_) void g_blurW_kernel(const float* __restrict__ guid) {
    __shared__ float row[W_ + 2*RAD];
    const int w = threadIdx.x;
    const int h = blockIdx.x, d = blockIdx.y, b = blockIdx.z;
    size_t r0 = (((size_t)(b*2+0)*D_ + d)*H_ + h)*W_;
    size_t r1 = (((size_t)(b*2+1)*D_ + d)*H_ + h)*W_;
    float v = (guid[r0+w] != 0.0f ? 1.0f : 0.0f) + (guid[r1+w] != 0.0f ? 1.0f : 0.0f);
    row[w + RAD] = v;
    if (w < RAD) { row[w] = 0.0f; row[w + W_ + RAD] = 0.0f; }
    __syncthreads();
    float acc = 0.0f;
#pragma unroll
    for (int j = 0; j < KLEN; j++) acc += d_gauss[j] * row[w + j];
    d_g[(((size_t)b*D_ + d)*H_ + h)*W_ + w] = acc;
}

// Blur along W for mag, IN PLACE (row fully staged in smem before writeback).
__global__ __launch_bounds__(W_) void blurW_mag_kernel() {
    __shared__ float row[W_ + 2*RAD];
    const int w = threadIdx.x;
    const int h = blockIdx.x, d = blockIdx.y, b = blockIdx.z;
    size_t base = (((size_t)b*D_ + d)*H_ + h)*W_;
    row[w + RAD] = d_mag[base + w];
    if (w < RAD) { row[w] = 0.0f; row[w + W_ + RAD] = 0.0f; }
    __syncthreads();
    float acc = 0.0f;
#pragma unroll
    for (int j = 0; j < KLEN; j++) acc += d_gauss[j] * row[w + j];
    d_mag[base + w] = acc;
}

// ---------------------------------------------------------------------------
// Blur along H for BOTH fields, IN PLACE (column fully staged before writes).
// Block covers 16 w's (16x16 threads), full H column, one (d,b).
// Smem: 2 * 216 * 16 * 4 = 27648 B (< 48KB static limit).
__global__ __launch_bounds__(256) void blurH_both_kernel() {
    __shared__ float shm[H_ + 2*RAD][16];
    __shared__ float shg[H_ + 2*RAD][16];
    const int tx = threadIdx.x, ty = threadIdx.y;       // 16 x 16
    const int w0 = blockIdx.x * 16, d = blockIdx.y, b = blockIdx.z;
    size_t base = ((size_t)b*D_ + d)*H_*W_;
    for (int hl = ty; hl < H_ + 2*RAD; hl += 16) {
        int gh = hl - RAD;
        bool ok = (unsigned)gh < (unsigned)H_;
        size_t idx = base + (size_t)(ok ? gh : 0)*W_ + w0 + tx;
        shm[hl][tx] = ok ? d_mag[idx] : 0.0f;
        shg[hl][tx] = ok ? d_g[idx]   : 0.0f;
    }
    __syncthreads();
    for (int h = ty; h < H_; h += 16) {
        float am = 0.0f, ag = 0.0f;
#pragma unroll
        for (int j = 0; j < KLEN; j++) {
            float gk = d_gauss[j];
            am += gk * shm[h + j][tx];
            ag += gk * shg[h + j][tx];
        }
        size_t idx = base + (size_t)h*W_ + w0 + tx;
        d_mag[idx] = am;
        d_g[idx]   = ag;
    }
}

// ---------------------------------------------------------------------------
// Blur along D for BOTH fields + fused dot-product / sum reduction.
// Deterministic: per-block partials, reduced in finalize.
// Smem: 2 * 120 * 32 * 4 + 2 KB = ~32.7 KB.
__global__ __launch_bounds__(256) void blurD_reduce_kernel() {
    __shared__ float shm[D_ + 2*RAD][32];
    __shared__ float shg[D_ + 2*RAD][32];
    __shared__ float rn[256], rd[256];
    const int tx = threadIdx.x, ty = threadIdx.y;
    const int tid = ty * 32 + tx;
    const int w0 = blockIdx.x * 32, h = blockIdx.y, b = blockIdx.z;
    size_t base = (size_t)b*VOL + (size_t)h*W_ + w0 + tx;
    for (int dl = ty; dl < D_ + 2*RAD; dl += 8) {
        int gd = dl - RAD;
        bool ok = (unsigned)gd < (unsigned)D_;
        size_t idx = base + (size_t)(ok ? gd : 0) * (H_*W_);
        shm[dl][tx] = ok ? d_mag[idx] : 0.0f;
        shg[dl][tx] = ok ? d_g[idx]   : 0.0f;
    }
    __syncthreads();
    float num = 0.0f, den = 0.0f;
    for (int dd = ty; dd < D_; dd += 8) {
        float vm = 0.0f, vg = 0.0f;
#pragma unroll
        for (int j = 0; j < KLEN; j++) {
            float gk = d_gauss[j];
            vm += gk * shm[dd + j][tx];
            vg += gk * shg[dd + j][tx];
        }
        num += vm * vg;
        den += vg;
    }
    rn[tid] = num; rd[tid] = den;
    __syncthreads();
    for (int s = 128; s > 0; s >>= 1) {
        if (tid < s) { rn[tid] += rn[tid + s]; rd[tid] += rd[tid + s]; }
        __syncthreads();
    }
    if (tid == 0) {
        int pb = blockIdx.y * gridDim.x + blockIdx.x;   // 0..NPART-1
        d_pnum[b*NPART + pb] = rn[0];
        d_pden[b*NPART + pb] = rd[0];
    }
}

// ---------------------------------------------------------------------------
__global__ __launch_bounds__(256) void finalize_kernel(float* __restrict__ out) {
    const int b = blockIdx.x, tid = threadIdx.x;
    __shared__ float rn[256], rd[256];
    float n = 0.0f, dsum = 0.0f;
    for (int i = tid; i < NPART; i += 256) {
        n    += d_pnum[b*NPART + i];
        dsum += d_pden[b*NPART + i];
    }
    rn[tid] = n; rd[tid] = dsum;
    __syncthreads();
    for (int s = 128; s > 0; s >>= 1) {
        if (tid < s) { rn[tid] += rn[tid + s]; rd[tid] += rd[tid + s]; }
        __syncthreads();
    }
    if (tid == 0) out[b] = expf(-(rn[0] / (rd[0] + 1.0f)));
}

// ---------------------------------------------------------------------------
extern "C" void kernel_launch(void* const* d_in, const int* in_sizes, int n_in,
                              void* d_out, int out_size) {
    (void)in_sizes; (void)n_in; (void)out_size;
    const float* outs = (const float*)d_in[0];
    const float* guid = (const float*)d_in[1];
    float* out = (float*)d_out;

    init_gauss_kernel<<<1, 32>>>();

    {   // fused round/sum + Sobel + magnitude  -> d_mag
        dim3 grid(W_/32, H_/8, B_ * NSLAB);
        dim3 blk(32, 8);
        sobel_mag_kernel<<<grid, blk>>>(outs);
    }
    {   // fused Gsum + W-blur -> d_g
        dim3 grid(H_, D_, B_);
        g_blurW_kernel<<<grid, W_>>>(guid);
    }
    {   // mag W-blur in place
        dim3 grid(H_, D_, B_);
        blurW_mag_kernel<<<grid, W_>>>();
    }
    {   // H-blur both fields in place
        dim3 grid(W_/16, D_, B_);
        dim3 blk(16, 16);
        blurH_both_kernel<<<grid, blk>>>();
    }
    {   // D-blur + reduction over d_mag, d_g -> partials
        dim3 grid(W_/32, H_, B_);
        dim3 blk(32, 8);
        blurD_reduce_kernel<<<grid, blk>>>();
    }
    finalize_kernel<<<B_, 256>>>(out);
}

// round 5
// speedup vs baseline: 1.4384x; 1.4384x over previous
#include <cuda_runtime.h>
#include <math.h>

#define D_ 96
#define H_ 192
#define W_ 192
#define B_ 2
#define VOL (D_*H_*W_)            // 3538944
#define RAD 12
#define KLEN 25
#define SLAB 16
#define NSLAB (D_/SLAB)           // 6
#define NPART ( (W_/32) * H_ )    // 1152 partials per batch

// ---- static scratch ----
__device__ float d_mag[B_*VOL];
__device__ float d_g  [B_*VOL];
__device__ float d_gauss[KLEN];
__device__ float d_pnum[B_*NPART];
__device__ float d_pden[B_*NPART];

// ---------------------------------------------------------------------------
__global__ void init_gauss_kernel() {
    int t = threadIdx.x;
    if (t < KLEN) {
        float x = (float)(t - RAD);
        const float c = 0.70710678f / 3.0f;
        float k = 0.5f * (erff(c * (x + 0.5f)) - erff(c * (x - 0.5f)));
        d_gauss[t] = fmaxf(k, 0.0f);
    }
}

// ---------------------------------------------------------------------------
// Fused: S = rint(o0)+rint(o1); 3D Sobel magnitude. Rolling 3-plane smem.
__global__ __launch_bounds__(256) void sobel_mag_kernel(const float* __restrict__ outs) {
    __shared__ float sh[3][10][34];
    const int tx = threadIdx.x, ty = threadIdx.y;
    const int tid = ty * 32 + tx;
    const int w0 = blockIdx.x * 32, h0 = blockIdx.y * 8;
    const int bz = blockIdx.z;
    const int b = bz / NSLAB;
    const int d0 = (bz % NSLAB) * SLAB;
    const float* o0 = outs + (size_t)(b * 2 + 0) * VOL;
    const float* o1 = outs + (size_t)(b * 2 + 1) * VOL;

    auto loadPlane = [&](int d, int slot) {
        for (int i = tid; i < 340; i += 256) {
            int lh = i / 34, lw = i - lh * 34;
            int gh = h0 + lh - 1, gw = w0 + lw - 1;
            float s = 0.0f;
            if ((unsigned)d < (unsigned)D_ && (unsigned)gh < (unsigned)H_ &&
                (unsigned)gw < (unsigned)W_) {
                int idx = (d * H_ + gh) * W_ + gw;
                s = rintf(__ldg(o0 + idx)) + rintf(__ldg(o1 + idx));
            }
            sh[slot][lh][lw] = s;
        }
    };

    loadPlane(d0 - 1, d0 % 3);
    loadPlane(d0,     (d0 + 1) % 3);

    const int lh = ty + 1, lw = tx + 1;
    for (int d = d0; d < d0 + SLAB; d++) {
        loadPlane(d + 1, (d + 2) % 3);
        __syncthreads();
        const float (*P)[34] = sh[d % 3];
        const float (*C)[34] = sh[(d + 1) % 3];
        const float (*N)[34] = sh[(d + 2) % 3];
        float c_mm = C[lh-1][lw-1], c_m0 = C[lh-1][lw], c_mp = C[lh-1][lw+1];
        float c_0m = C[lh  ][lw-1],                     c_0p = C[lh  ][lw+1];
        float c_pm = C[lh+1][lw-1], c_p0 = C[lh+1][lw], c_pp = C[lh+1][lw+1];
        float xv = (c_pm + 2.0f*c_p0 + c_pp) - (c_mm + 2.0f*c_m0 + c_mp);
        float xh = (c_mp + 2.0f*c_0p + c_pp) - (c_mm + 2.0f*c_0m + c_pm);
        float xd = (P[lh+1][lw] - P[lh-1][lw]) + 2.0f*(c_p0 - c_m0)
                 + (N[lh+1][lw] - N[lh-1][lw]);
        float mag = sqrtf(xv*xv + xh*xh + xd*xd + 1e-6f);
        d_mag[(size_t)b*VOL + ((size_t)d*H_ + (h0+ty))*W_ + (w0+tx)] = mag;
        __syncthreads();
    }
}

// ---------------------------------------------------------------------------
// W-blur for BOTH fields in one kernel. mag in place; g produced from guid.
// Each thread: 6 consecutive outputs, register-streaming window (30 LDS/field),
// 6 independent accumulator chains per field.
__global__ __launch_bounds__(256) void blurW_both_kernel(const float* __restrict__ guid) {
    __shared__ float sm[8][W_ + 2*RAD];   // 8 x 216
    __shared__ float sg[8][W_ + 2*RAD];
    const int tx = threadIdx.x, ty = threadIdx.y;   // 32 x 8
    const int h = blockIdx.x * 8 + ty, d = blockIdx.y, b = blockIdx.z;
    size_t base = (((size_t)b*D_ + d)*H_ + h)*W_;
    size_t r0 = (((size_t)(b*2+0)*D_ + d)*H_ + h)*W_;
    size_t r1 = (((size_t)(b*2+1)*D_ + d)*H_ + h)*W_;

    float kr[KLEN];
#pragma unroll
    for (int t = 0; t < KLEN; t++) kr[t] = d_gauss[t];

    for (int i = tx; i < W_ + 2*RAD; i += 32) {
        int gw = i - RAD;
        bool ok = (unsigned)gw < (unsigned)W_;
        sm[ty][i] = ok ? d_mag[base + gw] : 0.0f;
        float gv = 0.0f;
        if (ok) gv = (guid[r0+gw] != 0.0f ? 1.0f : 0.0f)
                   + (guid[r1+gw] != 0.0f ? 1.0f : 0.0f);
        sg[ty][i] = gv;
    }
    __syncthreads();

    const int wb = tx * 6;
    float am[6] = {0,0,0,0,0,0}, ag[6] = {0,0,0,0,0,0};
#pragma unroll
    for (int j = 0; j < 6 + 2*RAD; j++) {      // 30
        float xm = sm[ty][wb + j];
        float xg = sg[ty][wb + j];
#pragma unroll
        for (int i = 0; i < 6; i++) {
            int t = j - i;
            if (t >= 0 && t < KLEN) { am[i] += kr[t]*xm; ag[i] += kr[t]*xg; }
        }
    }
#pragma unroll
    for (int i = 0; i < 6; i++) {
        d_mag[base + wb + i] = am[i];
        d_g  [base + wb + i] = ag[i];
    }
}

// ---------------------------------------------------------------------------
// H-blur for BOTH fields, in place. 16x16 block, 16 w-columns, full H.
// Row pad 20 floats: half-warp h-offset 12 rows -> 12*20 = 240 = 16 mod 32,
// so the two 16-lane groups hit disjoint bank halves (conflict-free).
// Each thread: 12 consecutive h outputs per field, streaming window (36 LDS).
#define HP (H_ + 2*RAD)   // 216
__global__ __launch_bounds__(256) void blurH_both_kernel() {
    __shared__ float sm[HP][20];
    __shared__ float sg[HP][20];
    const int tx = threadIdx.x, ty = threadIdx.y;   // 16 x 16
    const int w0 = blockIdx.x * 16, d = blockIdx.y, b = blockIdx.z;
    size_t base = ((size_t)b*D_ + d) * (size_t)(H_*W_);

    float kr[KLEN];
#pragma unroll
    for (int t = 0; t < KLEN; t++) kr[t] = d_gauss[t];

    for (int hl = ty; hl < HP; hl += 16) {
        int gh = hl - RAD;
        bool ok = (unsigned)gh < (unsigned)H_;
        size_t idx = base + (size_t)(ok ? gh : 0)*W_ + w0 + tx;
        sm[hl][tx] = ok ? d_mag[idx] : 0.0f;
        sg[hl][tx] = ok ? d_g[idx]   : 0.0f;
    }
    __syncthreads();

    const int hb = ty * 12;
    {   // mag
        float a[12] = {0,0,0,0,0,0,0,0,0,0,0,0};
#pragma unroll
        for (int j = 0; j < 12 + 2*RAD; j++) {  // 36
            float x = sm[hb + j][tx];
#pragma unroll
            for (int i = 0; i < 12; i++) {
                int t = j - i;
                if (t >= 0 && t < KLEN) a[i] += kr[t]*x;
            }
        }
#pragma unroll
        for (int i = 0; i < 12; i++)
            d_mag[base + (size_t)(hb+i)*W_ + w0 + tx] = a[i];
    }
    {   // g
        float a[12] = {0,0,0,0,0,0,0,0,0,0,0,0};
#pragma unroll
        for (int j = 0; j < 12 + 2*RAD; j++) {
            float x = sg[hb + j][tx];
#pragma unroll
            for (int i = 0; i < 12; i++) {
                int t = j - i;
                if (t >= 0 && t < KLEN) a[i] += kr[t]*x;
            }
        }
#pragma unroll
        for (int i = 0; i < 12; i++)
            d_g[base + (size_t)(hb+i)*W_ + w0 + tx] = a[i];
    }
}

// ---------------------------------------------------------------------------
// D-blur both fields + fused dot/sum reduction. 32x8 block; each thread
// 12 consecutive d outputs per field, streaming window; conflict-free
// (full warp reads one smem row; row stride 32 floats).
__global__ __launch_bounds__(256) void blurD_reduce_kernel() {
    __shared__ float sm[D_ + 2*RAD][32];  // 120 x 32
    __shared__ float sg[D_ + 2*RAD][32];
    __shared__ float rn[256], rd[256];
    const int tx = threadIdx.x, ty = threadIdx.y;
    const int tid = ty * 32 + tx;
    const int w0 = blockIdx.x * 32, h = blockIdx.y, b = blockIdx.z;
    size_t base = (size_t)b*VOL + (size_t)h*W_ + w0 + tx;

    float kr[KLEN];
#pragma unroll
    for (int t = 0; t < KLEN; t++) kr[t] = d_gauss[t];

    for (int dl = ty; dl < D_ + 2*RAD; dl += 8) {
        int gd = dl - RAD;
        bool ok = (unsigned)gd < (unsigned)D_;
        size_t idx = base + (size_t)(ok ? gd : 0) * (H_*W_);
        sm[dl][tx] = ok ? d_mag[idx] : 0.0f;
        sg[dl][tx] = ok ? d_g[idx]   : 0.0f;
    }
    __syncthreads();

    const int db = ty * 12;
    float am[12] = {0,0,0,0,0,0,0,0,0,0,0,0};
    float ag[12] = {0,0,0,0,0,0,0,0,0,0,0,0};
#pragma unroll
    for (int j = 0; j < 12 + 2*RAD; j++) {  // 36
        float xm = sm[db + j][tx];
        float xg = sg[db + j][tx];
#pragma unroll
        for (int i = 0; i < 12; i++) {
            int t = j - i;
            if (t >= 0 && t < KLEN) { am[i] += kr[t]*xm; ag[i] += kr[t]*xg; }
        }
    }
    float num = 0.0f, den = 0.0f;
#pragma unroll
    for (int i = 0; i < 12; i++) { num += am[i]*ag[i]; den += ag[i]; }

    rn[tid] = num; rd[tid] = den;
    __syncthreads();
    for (int s = 128; s > 0; s >>= 1) {
        if (tid < s) { rn[tid] += rn[tid + s]; rd[tid] += rd[tid + s]; }
        __syncthreads();
    }
    if (tid == 0) {
        int pb = blockIdx.y * gridDim.x + blockIdx.x;
        d_pnum[b*NPART + pb] = rn[0];
        d_pden[b*NPART + pb] = rd[0];
    }
}

// ---------------------------------------------------------------------------
__global__ __launch_bounds__(256) void finalize_kernel(float* __restrict__ out) {
    const int b = blockIdx.x, tid = threadIdx.x;
    __shared__ float rn[256], rd[256];
    float n = 0.0f, dsum = 0.0f;
    for (int i = tid; i < NPART; i += 256) {
        n    += d_pnum[b*NPART + i];
        dsum += d_pden[b*NPART + i];
    }
    rn[tid] = n; rd[tid] = dsum;
    __syncthreads();
    for (int s = 128; s > 0; s >>= 1) {
        if (tid < s) { rn[tid] += rn[tid + s]; rd[tid] += rd[tid + s]; }
        __syncthreads();
    }
    if (tid == 0) out[b] = expf(-(rn[0] / (rd[0] + 1.0f)));
}

// ---------------------------------------------------------------------------
extern "C" void kernel_launch(void* const* d_in, const int* in_sizes, int n_in,
                              void* d_out, int out_size) {
    (void)in_sizes; (void)n_in; (void)out_size;
    const float* outs = (const float*)d_in[0];
    const float* guid = (const float*)d_in[1];
    float* out = (float*)d_out;

    init_gauss_kernel<<<1, 32>>>();

    {   // Sobel magnitude -> d_mag
        dim3 grid(W_/32, H_/8, B_ * NSLAB);
        dim3 blk(32, 8);
        sobel_mag_kernel<<<grid, blk>>>(outs);
    }
    {   // W-blur: mag in place + guid -> g
        dim3 grid(H_/8, D_, B_);
        dim3 blk(32, 8);
        blurW_both_kernel<<<grid, blk>>>(guid);
    }
    {   // H-blur both fields in place
        dim3 grid(W_/16, D_, B_);
        dim3 blk(16, 16);
        blurH_both_kernel<<<grid, blk>>>();
    }
    {   // D-blur + reduction
        dim3 grid(W_/32, H_, B_);
        dim3 blk(32, 8);
        blurD_reduce_kernel<<<grid, blk>>>();
    }
    finalize_kernel<<<B_, 256>>>(out);
}

// round 6
// speedup vs baseline: 1.8068x; 1.2561x over previous
#include <cuda_runtime.h>
#include <math.h>

#define D_ 96
#define H_ 192
#define W_ 192
#define B_ 2
#define VOL (D_*H_*W_)            // 3538944
#define RAD 12
#define KLEN 25
#define SLAB 8
#define NSLAB (D_/SLAB)           // 12
#define PW (W_ + 2)               // 194 (sobel halo)
#define WB (W_ + 2*RAD)           // 216 (blur window)
#define HP (H_ + 2*RAD)           // 216
#define DP (D_ + 2*RAD)           // 120
#define NPART ((W_/32) * H_)      // 1152 partials per batch

// ---- static scratch ----
__device__ float2 d_mg[B_*VOL];   // interleaved {mag, g}
__device__ float  d_gauss[KLEN];
__device__ float  d_pnum[B_*NPART];
__device__ float  d_pden[B_*NPART];

// ---------------------------------------------------------------------------
__global__ void init_gauss_kernel() {
    int t = threadIdx.x;
    if (t < KLEN) {
        float x = (float)(t - RAD);
        const float c = 0.70710678f / 3.0f;
        float k = 0.5f * (erff(c * (x + 0.5f)) - erff(c * (x - 0.5f)));
        d_gauss[t] = fmaxf(k, 0.0f);
    }
}

// tap lookup with symmetry (t in [0,25))
#define TAP(t) kr[(t) < 13 ? (t) : 24 - (t)]

// ---------------------------------------------------------------------------
// K1: fused  S=rint(o0)+rint(o1) -> 3D Sobel magnitude -> W-blur(mag)
//     and    Gsum=(g0!=0)+(g1!=0) -> W-blur(g)
// writes interleaved float2 {magW, gW} to d_mg. One read of outs+guid, one write.
// Block (32,8): 8 h-rows, full W, SLAB d's (rolling 3-plane smem).
__global__ __launch_bounds__(256) void sobel_blurW_kernel(const float* __restrict__ outs,
                                                          const float* __restrict__ guid) {
    __shared__ float pl[3][10][PW];    // 3 planes, 8+2 rows, W+2 cols
    __shared__ float mb[8][WB];        // mag rows (zero-padded by RAD)
    __shared__ float gb[8][WB];        // g rows
    const int tx = threadIdx.x, ty = threadIdx.y;
    const int tid = ty * 32 + tx;
    const int h0 = blockIdx.x * 8;
    const int d0 = blockIdx.y * SLAB;
    const int b  = blockIdx.z;
    const float* o0 = outs + (size_t)(b*2+0)*VOL;
    const float* o1 = outs + (size_t)(b*2+1)*VOL;
    const float* g0 = guid + (size_t)(b*2+0)*VOL;
    const float* g1 = guid + (size_t)(b*2+1)*VOL;

    float kr[13];
#pragma unroll
    for (int t = 0; t < 13; t++) kr[t] = d_gauss[t];

    // zero the RAD halos of the row buffers (only interior written later)
    if (tx < RAD) {
        mb[ty][tx] = 0.0f; mb[ty][W_ + RAD + tx] = 0.0f;
        gb[ty][tx] = 0.0f; gb[ty][W_ + RAD + tx] = 0.0f;
    }

    auto loadPlane = [&](int d, int slot) {
        for (int i = tid; i < 10 * PW; i += 256) {
            int lh = i / PW, lw = i - lh * PW;
            int gh = h0 + lh - 1, gw = lw - 1;
            float s = 0.0f;
            if ((unsigned)d < (unsigned)D_ && (unsigned)gh < (unsigned)H_ &&
                (unsigned)gw < (unsigned)W_) {
                int idx = (d * H_ + gh) * W_ + gw;
                s = rintf(__ldg(o0 + idx)) + rintf(__ldg(o1 + idx));
            }
            pl[slot][lh][lw] = s;
        }
    };

    loadPlane(d0 - 1, d0 % 3);
    loadPlane(d0,     (d0 + 1) % 3);

    const int h = h0 + ty, lh = ty + 1;
    for (int d = d0; d < d0 + SLAB; d++) {
        loadPlane(d + 1, (d + 2) % 3);
        __syncthreads();
        const float (*P)[PW] = pl[d % 3];
        const float (*C)[PW] = pl[(d + 1) % 3];
        const float (*N)[PW] = pl[(d + 2) % 3];
#pragma unroll
        for (int c = 0; c < 6; c++) {
            int w = c * 32 + tx, lw = w + 1;
            float c_mm = C[lh-1][lw-1], c_m0 = C[lh-1][lw], c_mp = C[lh-1][lw+1];
            float c_0m = C[lh  ][lw-1],                     c_0p = C[lh  ][lw+1];
            float c_pm = C[lh+1][lw-1], c_p0 = C[lh+1][lw], c_pp = C[lh+1][lw+1];
            float xv = (c_pm + 2.0f*c_p0 + c_pp) - (c_mm + 2.0f*c_m0 + c_mp);
            float xh = (c_mp + 2.0f*c_0p + c_pp) - (c_mm + 2.0f*c_0m + c_pm);
            float xd = (P[lh+1][lw] - P[lh-1][lw]) + 2.0f*(c_p0 - c_m0)
                     + (N[lh+1][lw] - N[lh-1][lw]);
            mb[ty][RAD + w] = sqrtf(xv*xv + xh*xh + xd*xd + 1e-6f);
            int gidx = (d * H_ + h) * W_ + w;
            gb[ty][RAD + w] = (__ldg(g0 + gidx) != 0.0f ? 1.0f : 0.0f)
                            + (__ldg(g1 + gidx) != 0.0f ? 1.0f : 0.0f);
        }
        __syncwarp();
        // W-blur: 6 outputs/thread, streaming 30-wide window (warp-local rows)
        const int wb = tx * 6;
        float am[6] = {0,0,0,0,0,0}, ag[6] = {0,0,0,0,0,0};
#pragma unroll
        for (int j = 0; j < 6 + 2*RAD; j++) {
            float xm = mb[ty][wb + j];
            float xg = gb[ty][wb + j];
#pragma unroll
            for (int i = 0; i < 6; i++) {
                int t = j - i;
                if (t >= 0 && t < KLEN) {
                    float k = TAP(t);
                    am[i] += k * xm; ag[i] += k * xg;
                }
            }
        }
        size_t base = (((size_t)b*D_ + d)*H_ + h)*W_ + wb;
#pragma unroll
        for (int i = 0; i < 6; i++) d_mg[base + i] = make_float2(am[i], ag[i]);
        __syncthreads();
    }
}

// ---------------------------------------------------------------------------
// K2: H-blur both fields (float2), in place. Block (16,16), 16 w-cols, full H.
// Each thread: 12 consecutive h outputs, streaming 36-wide window of float2.
__global__ __launch_bounds__(256) void blurH_kernel() {
    __shared__ float2 sh[HP][16];      // 27648 B
    const int tx = threadIdx.x, ty = threadIdx.y;
    const int w0 = blockIdx.x * 16, d = blockIdx.y, b = blockIdx.z;
    size_t base = ((size_t)b*D_ + d) * (size_t)(H_*W_);

    float kr[13];
#pragma unroll
    for (int t = 0; t < 13; t++) kr[t] = d_gauss[t];

    for (int hl = ty; hl < HP; hl += 16) {
        int gh = hl - RAD;
        bool ok = (unsigned)gh < (unsigned)H_;
        size_t idx = base + (size_t)(ok ? gh : 0)*W_ + w0 + tx;
        sh[hl][tx] = ok ? d_mg[idx] : make_float2(0.0f, 0.0f);
    }
    __syncthreads();

    const int hb = ty * 12;
    float am[12] = {0,0,0,0,0,0,0,0,0,0,0,0};
    float ag[12] = {0,0,0,0,0,0,0,0,0,0,0,0};
#pragma unroll
    for (int j = 0; j < 12 + 2*RAD; j++) {
        float2 x = sh[hb + j][tx];
#pragma unroll
        for (int i = 0; i < 12; i++) {
            int t = j - i;
            if (t >= 0 && t < KLEN) {
                float k = TAP(t);
                am[i] += k * x.x; ag[i] += k * x.y;
            }
        }
    }
#pragma unroll
    for (int i = 0; i < 12; i++)
        d_mg[base + (size_t)(hb+i)*W_ + w0 + tx] = make_float2(am[i], ag[i]);
}

// ---------------------------------------------------------------------------
// K3: D-blur both fields (float2) + fused dot/sum reduction.
__global__ __launch_bounds__(256) void blurD_reduce_kernel() {
    __shared__ float2 sh[DP][32];      // 30720 B
    __shared__ float rn[256], rd[256];
    const int tx = threadIdx.x, ty = threadIdx.y;
    const int tid = ty * 32 + tx;
    const int w0 = blockIdx.x * 32, h = blockIdx.y, b = blockIdx.z;
    size_t base = (size_t)b*VOL + (size_t)h*W_ + w0 + tx;

    float kr[13];
#pragma unroll
    for (int t = 0; t < 13; t++) kr[t] = d_gauss[t];

    for (int dl = ty; dl < DP; dl += 8) {
        int gd = dl - RAD;
        bool ok = (unsigned)gd < (unsigned)D_;
        size_t idx = base + (size_t)(ok ? gd : 0) * (H_*W_);
        sh[dl][tx] = ok ? d_mg[idx] : make_float2(0.0f, 0.0f);
    }
    __syncthreads();

    const int db = ty * 12;
    float am[12] = {0,0,0,0,0,0,0,0,0,0,0,0};
    float ag[12] = {0,0,0,0,0,0,0,0,0,0,0,0};
#pragma unroll
    for (int j = 0; j < 12 + 2*RAD; j++) {
        float2 x = sh[db + j][tx];
#pragma unroll
        for (int i = 0; i < 12; i++) {
            int t = j - i;
            if (t >= 0 && t < KLEN) {
                float k = TAP(t);
                am[i] += k * x.x; ag[i] += k * x.y;
            }
        }
    }
    float num = 0.0f, den = 0.0f;
#pragma unroll
    for (int i = 0; i < 12; i++) { num += am[i]*ag[i]; den += ag[i]; }

    rn[tid] = num; rd[tid] = den;
    __syncthreads();
    for (int s = 128; s > 0; s >>= 1) {
        if (tid < s) { rn[tid] += rn[tid + s]; rd[tid] += rd[tid + s]; }
        __syncthreads();
    }
    if (tid == 0) {
        int pb = blockIdx.y * gridDim.x + blockIdx.x;
        d_pnum[b*NPART + pb] = rn[0];
        d_pden[b*NPART + pb] = rd[0];
    }
}

// ---------------------------------------------------------------------------
__global__ __launch_bounds__(256) void finalize_kernel(float* __restrict__ out) {
    const int b = blockIdx.x, tid = threadIdx.x;
    __shared__ float rn[256], rd[256];
    float n = 0.0f, dsum = 0.0f;
    for (int i = tid; i < NPART; i += 256) {
        n    += d_pnum[b*NPART + i];
        dsum += d_pden[b*NPART + i];
    }
    rn[tid] = n; rd[tid] = dsum;
    __syncthreads();
    for (int s = 128; s > 0; s >>= 1) {
        if (tid < s) { rn[tid] += rn[tid + s]; rd[tid] += rd[tid + s]; }
        __syncthreads();
    }
    if (tid == 0) out[b] = expf(-(rn[0] / (rd[0] + 1.0f)));
}

// ---------------------------------------------------------------------------
extern "C" void kernel_launch(void* const* d_in, const int* in_sizes, int n_in,
                              void* d_out, int out_size) {
    (void)in_sizes; (void)n_in; (void)out_size;
    const float* outs = (const float*)d_in[0];
    const float* guid = (const float*)d_in[1];
    float* out = (float*)d_out;

    init_gauss_kernel<<<1, 32>>>();
    {   // fused sobel + W-blur (both fields) -> d_mg
        dim3 grid(H_/8, NSLAB, B_);
        dim3 blk(32, 8);
        sobel_blurW_kernel<<<grid, blk>>>(outs, guid);
    }
    {   // H-blur (both fields) in place
        dim3 grid(W_/16, D_, B_);
        dim3 blk(16, 16);
        blurH_kernel<<<grid, blk>>>();
    }
    {   // D-blur + reduction
        dim3 grid(W_/32, H_, B_);
        dim3 blk(32, 8);
        blurD_reduce_kernel<<<grid, blk>>>();
    }
    finalize_kernel<<<B_, 256>>>(out);
}

// round 7
// speedup vs baseline: 1.8794x; 1.0402x over previous
#include <cuda_runtime.h>
#include <math.h>

#define D_ 96
#define H_ 192
#define W_ 192
#define B_ 2
#define VOL (D_*H_*W_)            // 3538944
#define RAD 12
#define KLEN 25
#define SLAB 8
#define NSLAB (D_/SLAB)           // 12
#define PW (W_ + 2)               // 194 (sobel halo)
#define WB (W_ + 2*RAD)           // 216 (blur window)
#define HP (H_ + 2*RAD)           // 216
#define DP (D_ + 2*RAD)           // 120
#define NPART ((W_/32) * H_)      // 1152 partials per batch

typedef unsigned long long u64;

// ---- static scratch ----
__device__ u64   d_mg[B_*VOL];    // packed {mag, g} as f32x2
__device__ float d_gauss[KLEN];
__device__ float d_pnum[B_*NPART];
__device__ float d_pden[B_*NPART];

// ---------------------------------------------------------------------------
// packed f32x2 helpers (Blackwell)
__device__ __forceinline__ u64 pack2(float a, float b) {
    u64 r; asm("mov.b64 %0, {%1,%2};" : "=l"(r) : "f"(a), "f"(b)); return r;
}
__device__ __forceinline__ void fma2(u64& d, u64 a, u64 b) {
    asm("fma.rn.f32x2 %0, %1, %2, %3;" : "=l"(d) : "l"(a), "l"(b), "l"(d));
}
__device__ __forceinline__ float2 unpack2(u64 v) {
    float x, y; asm("mov.b64 {%0,%1}, %2;" : "=f"(x), "=f"(y) : "l"(v));
    return make_float2(x, y);
}

// tap lookup with symmetry (t in [0,25)), packed {k,k}
#define TAP2(t) kp[(t) < 13 ? (t) : 24 - (t)]

// ---------------------------------------------------------------------------
__global__ void init_gauss_kernel() {
    int t = threadIdx.x;
    if (t < KLEN) {
        float x = (float)(t - RAD);
        const float c = 0.70710678f / 3.0f;
        float k = 0.5f * (erff(c * (x + 0.5f)) - erff(c * (x - 0.5f)));
        d_gauss[t] = fmaxf(k, 0.0f);
    }
}

// ---------------------------------------------------------------------------
// K1: fused  S=rint(o0)+rint(o1) -> 3D Sobel magnitude  and  Gsum binarize,
// then W-blur of BOTH via packed fma2. Writes packed {magW,gW} to d_mg.
__global__ __launch_bounds__(256) void sobel_blurW_kernel(const float* __restrict__ outs,
                                                          const float* __restrict__ guid) {
    __shared__ float pl[3][10][PW];    // 3 planes, 8+2 rows, W+2 cols (23.3 KB)
    __shared__ u64   wg[8][WB];        // packed {mag,g} rows (13.8 KB)
    const int tx = threadIdx.x, ty = threadIdx.y;
    const int tid = ty * 32 + tx;
    const int h0 = blockIdx.x * 8;
    const int d0 = blockIdx.y * SLAB;
    const int b  = blockIdx.z;
    const float* o0 = outs + (size_t)(b*2+0)*VOL;
    const float* o1 = outs + (size_t)(b*2+1)*VOL;
    const float* g0 = guid + (size_t)(b*2+0)*VOL;
    const float* g1 = guid + (size_t)(b*2+1)*VOL;

    u64 kp[13];
#pragma unroll
    for (int t = 0; t < 13; t++) { float k = d_gauss[t]; kp[t] = pack2(k, k); }

    if (tx < RAD) {                    // zero halos (warp-private rows)
        wg[ty][tx] = 0ULL; wg[ty][W_ + RAD + tx] = 0ULL;
    }

    auto loadPlane = [&](int d, int slot) {
        for (int i = tid; i < 10 * PW; i += 256) {
            int lh = i / PW, lw = i - lh * PW;
            int gh = h0 + lh - 1, gw = lw - 1;
            float s = 0.0f;
            if ((unsigned)d < (unsigned)D_ && (unsigned)gh < (unsigned)H_ &&
                (unsigned)gw < (unsigned)W_) {
                int idx = (d * H_ + gh) * W_ + gw;
                s = rintf(__ldg(o0 + idx)) + rintf(__ldg(o1 + idx));
            }
            pl[slot][lh][lw] = s;
        }
    };

    loadPlane(d0 - 1, d0 % 3);
    loadPlane(d0,     (d0 + 1) % 3);

    const int h = h0 + ty, lh = ty + 1;
    for (int d = d0; d < d0 + SLAB; d++) {
        loadPlane(d + 1, (d + 2) % 3);
        __syncthreads();
        const float (*P)[PW] = pl[d % 3];
        const float (*C)[PW] = pl[(d + 1) % 3];
        const float (*N)[PW] = pl[(d + 2) % 3];
#pragma unroll
        for (int c = 0; c < 6; c++) {
            int w = c * 32 + tx, lw = w + 1;
            float c_mm = C[lh-1][lw-1], c_m0 = C[lh-1][lw], c_mp = C[lh-1][lw+1];
            float c_0m = C[lh  ][lw-1],                     c_0p = C[lh  ][lw+1];
            float c_pm = C[lh+1][lw-1], c_p0 = C[lh+1][lw], c_pp = C[lh+1][lw+1];
            float xv = (c_pm + 2.0f*c_p0 + c_pp) - (c_mm + 2.0f*c_m0 + c_mp);
            float xh = (c_mp + 2.0f*c_0p + c_pp) - (c_mm + 2.0f*c_0m + c_pm);
            float xd = (P[lh+1][lw] - P[lh-1][lw]) + 2.0f*(c_p0 - c_m0)
                     + (N[lh+1][lw] - N[lh-1][lw]);
            float mag = sqrtf(xv*xv + xh*xh + xd*xd + 1e-6f);
            int gidx = (d * H_ + h) * W_ + w;
            float gv = (__ldg(g0 + gidx) != 0.0f ? 1.0f : 0.0f)
                     + (__ldg(g1 + gidx) != 0.0f ? 1.0f : 0.0f);
            wg[ty][RAD + w] = pack2(mag, gv);
        }
        __syncwarp();
        // W-blur: 6 outputs/thread, 30-wide streaming window, packed fma
        const int wb = tx * 6;
        u64 acc[6] = {0,0,0,0,0,0};
#pragma unroll
        for (int j = 0; j < 6 + 2*RAD; j++) {
            u64 x = wg[ty][wb + j];
#pragma unroll
            for (int i = 0; i < 6; i++) {
                int t = j - i;
                if (t >= 0 && t < KLEN) fma2(acc[i], TAP2(t), x);
            }
        }
        size_t base = (((size_t)b*D_ + d)*H_ + h)*W_ + wb;
#pragma unroll
        for (int i = 0; i < 6; i++) d_mg[base + i] = acc[i];
        __syncthreads();
    }
}

// ---------------------------------------------------------------------------
// K2: H-blur both fields (packed), in place. Block (16,16), 16 w-cols, full H.
__global__ __launch_bounds__(256) void blurH_kernel() {
    __shared__ u64 sh[HP][16];         // 27648 B
    const int tx = threadIdx.x, ty = threadIdx.y;
    const int w0 = blockIdx.x * 16, d = blockIdx.y, b = blockIdx.z;
    size_t base = ((size_t)b*D_ + d) * (size_t)(H_*W_);

    u64 kp[13];
#pragma unroll
    for (int t = 0; t < 13; t++) { float k = d_gauss[t]; kp[t] = pack2(k, k); }

    for (int hl = ty; hl < HP; hl += 16) {
        int gh = hl - RAD;
        bool ok = (unsigned)gh < (unsigned)H_;
        size_t idx = base + (size_t)(ok ? gh : 0)*W_ + w0 + tx;
        sh[hl][tx] = ok ? d_mg[idx] : 0ULL;
    }
    __syncthreads();

    const int hb = ty * 12;
    u64 acc[12] = {0,0,0,0,0,0,0,0,0,0,0,0};
#pragma unroll
    for (int j = 0; j < 12 + 2*RAD; j++) {
        u64 x = sh[hb + j][tx];
#pragma unroll
        for (int i = 0; i < 12; i++) {
            int t = j - i;
            if (t >= 0 && t < KLEN) fma2(acc[i], TAP2(t), x);
        }
    }
#pragma unroll
    for (int i = 0; i < 12; i++)
        d_mg[base + (size_t)(hb+i)*W_ + w0 + tx] = acc[i];
}

// ---------------------------------------------------------------------------
// K3: D-blur both fields (packed) + fused dot/sum reduction.
__global__ __launch_bounds__(256) void blurD_reduce_kernel() {
    __shared__ u64 sh[DP][32];         // 30720 B
    __shared__ float rn[256], rd[256];
    const int tx = threadIdx.x, ty = threadIdx.y;
    const int tid = ty * 32 + tx;
    const int w0 = blockIdx.x * 32, h = blockIdx.y, b = blockIdx.z;
    size_t base = (size_t)b*VOL + (size_t)h*W_ + w0 + tx;

    u64 kp[13];
#pragma unroll
    for (int t = 0; t < 13; t++) { float k = d_gauss[t]; kp[t] = pack2(k, k); }

    for (int dl = ty; dl < DP; dl += 8) {
        int gd = dl - RAD;
        bool ok = (unsigned)gd < (unsigned)D_;
        size_t idx = base + (size_t)(ok ? gd : 0) * (H_*W_);
        sh[dl][tx] = ok ? d_mg[idx] : 0ULL;
    }
    __syncthreads();

    const int db = ty * 12;
    u64 acc[12] = {0,0,0,0,0,0,0,0,0,0,0,0};
#pragma unroll
    for (int j = 0; j < 12 + 2*RAD; j++) {
        u64 x = sh[db + j][tx];
#pragma unroll
        for (int i = 0; i < 12; i++) {
            int t = j - i;
            if (t >= 0 && t < KLEN) fma2(acc[i], TAP2(t), x);
        }
    }
    float num = 0.0f, den = 0.0f;
#pragma unroll
    for (int i = 0; i < 12; i++) {
        float2 v = unpack2(acc[i]);
        num += v.x * v.y;
        den += v.y;
    }

    rn[tid] = num; rd[tid] = den;
    __syncthreads();
    for (int s = 128; s > 0; s >>= 1) {
        if (tid < s) { rn[tid] += rn[tid + s]; rd[tid] += rd[tid + s]; }
        __syncthreads();
    }
    if (tid == 0) {
        int pb = blockIdx.y * gridDim.x + blockIdx.x;
        d_pnum[b*NPART + pb] = rn[0];
        d_pden[b*NPART + pb] = rd[0];
    }
}

// ---------------------------------------------------------------------------
__global__ __launch_bounds__(256) void finalize_kernel(float* __restrict__ out) {
    const int b = blockIdx.x, tid = threadIdx.x;
    __shared__ float rn[256], rd[256];
    float n = 0.0f, dsum = 0.0f;
    for (int i = tid; i < NPART; i += 256) {
        n    += d_pnum[b*NPART + i];
        dsum += d_pden[b*NPART + i];
    }
    rn[tid] = n; rd[tid] = dsum;
    __syncthreads();
    for (int s = 128; s > 0; s >>= 1) {
        if (tid < s) { rn[tid] += rn[tid + s]; rd[tid] += rd[tid + s]; }
        __syncthreads();
    }
    if (tid == 0) out[b] = expf(-(rn[0] / (rd[0] + 1.0f)));
}

// ---------------------------------------------------------------------------
extern "C" void kernel_launch(void* const* d_in, const int* in_sizes, int n_in,
                              void* d_out, int out_size) {
    (void)in_sizes; (void)n_in; (void)out_size;
    const float* outs = (const float*)d_in[0];
    const float* guid = (const float*)d_in[1];
    float* out = (float*)d_out;

    init_gauss_kernel<<<1, 32>>>();
    {   // fused sobel + W-blur (both fields, packed) -> d_mg
        dim3 grid(H_/8, NSLAB, B_);
        dim3 blk(32, 8);
        sobel_blurW_kernel<<<grid, blk>>>(outs, guid);
    }
    {   // H-blur (both fields, packed) in place
        dim3 grid(W_/16, D_, B_);
        dim3 blk(16, 16);
        blurH_kernel<<<grid, blk>>>();
    }
    {   // D-blur + reduction (packed)
        dim3 grid(W_/32, H_, B_);
        dim3 blk(32, 8);
        blurD_reduce_kernel<<<grid, blk>>>();
    }
    finalize_kernel<<<B_, 256>>>(out);
}